// round 8
// baseline (speedup 1.0000x reference)
#include <cuda_runtime.h>
#include <cuda_fp16.h>
#include <cfloat>
#include <cstdint>

#define Bq 2048
#define Nn 100000
#define Dd 512
#define BM 128
#define BN 128
#define BK 64                    // fp16 k-chunk (64 elts = 128 B = SW128 row)
#define NSPLIT 37
#define RPS 2703                 // ceil(Nn / NSPLIT)
#define NCAND (2 * NSPLIT)
#define MARGIN 2.0f
#define NT 512                   // threads (16 warps, 4 per SMSP)

#define TILES 22                 // ceil(RPS / 128)
#define KCH   8                  // k-chunks per tile (512/64)
#define CHUNKS (TILES * KCH)     // 176
#define STAGES 4

// dynamic smem layout (bytes)
#define SM_B2 0                              // TILES*128 floats = 11264
#define SM_A  12288                          // 8 chunks x 16384 = 131072 (resident)
#define SM_B  (SM_A + KCH * 16384)           // 4-stage ring x 16384
#define SMEM_TOTAL (SM_B + STAGES * 16384)   // 208896

// ---- device-global scratch (no allocs; zero-initialized) ----
__device__ __half g_qh[Bq * Dd];                  // 2 MB
__device__ __half g_bh[(Nn + 256) * Dd];          // ~102 MB (pad rows stay 0)
__device__ float g_b2[Nn];
__device__ float g_pv[NCAND * Bq];
__device__ int   g_pi[NCAND * Bq];

// ---------------------------------------------------------------------------
// helpers
// ---------------------------------------------------------------------------
__device__ __forceinline__ uint32_t swz128(uint32_t off) {   // SW128 swizzle
    return off ^ ((off >> 3) & 0x70u);
}
__device__ __forceinline__ void cpasync16(uint32_t dst, const void* src) {
    asm volatile("cp.async.cg.shared.global [%0], [%1], 16;" :: "r"(dst), "l"(src));
}
__device__ __forceinline__ void cp_commit() { asm volatile("cp.async.commit_group;"); }
template <int N>
__device__ __forceinline__ void cp_wait() { asm volatile("cp.async.wait_group %0;" :: "n"(N)); }
__device__ __forceinline__ void ldsm4(uint32_t& r0, uint32_t& r1, uint32_t& r2, uint32_t& r3,
                                      uint32_t a) {
    asm volatile("ldmatrix.sync.aligned.m8n8.x4.shared.b16 {%0,%1,%2,%3}, [%4];"
                 : "=r"(r0), "=r"(r1), "=r"(r2), "=r"(r3) : "r"(a));
}
// fp16 inputs, fp16 accumulators: D(2 x f16x2) = A(4) * B(2) + D
__device__ __forceinline__ void mma_h(uint32_t c[2], uint32_t a0, uint32_t a1, uint32_t a2,
                                      uint32_t a3, uint32_t b0, uint32_t b1) {
    asm volatile(
        "mma.sync.aligned.m16n8k16.row.col.f16.f16.f16.f16 "
        "{%0,%1},{%2,%3,%4,%5},{%6,%7},{%0,%1};"
        : "+r"(c[0]), "+r"(c[1])
        : "r"(a0), "r"(a1), "r"(a2), "r"(a3), "r"(b0), "r"(b1));
}
// lexicographic (value, index) less-than
__device__ __forceinline__ bool lex_lt(float a, int ia, float b, int ib) {
    return (a < b) || (a == b && ia < ib);
}

// ---------------------------------------------------------------------------
// Convert kernels: fp32 -> fp16 (convb also computes exact fp32 b2)
// ---------------------------------------------------------------------------
__global__ void knn_convq_kernel(const float* __restrict__ Q) {
    int i = blockIdx.x * 256 + threadIdx.x;      // float4 index
    float4 v = reinterpret_cast<const float4*>(Q)[i];
    __half2* dst = reinterpret_cast<__half2*>(g_qh);
    dst[2 * i]     = __floats2half2_rn(v.x, v.y);
    dst[2 * i + 1] = __floats2half2_rn(v.z, v.w);
}

__global__ void knn_convb_kernel(const float* __restrict__ Bf) {
    int warp = threadIdx.x >> 5, lane = threadIdx.x & 31;
    int row = blockIdx.x * 8 + warp;
    if (row >= Nn) return;
    const float4* src = reinterpret_cast<const float4*>(Bf + (size_t)row * Dd);
    __half2* dst = reinterpret_cast<__half2*>(g_bh + (size_t)row * Dd);
    float s = 0.f;
#pragma unroll
    for (int it = 0; it < 4; it++) {
        int c = lane + 32 * it;
        float4 v = src[c];
        s += v.x * v.x + v.y * v.y + v.z * v.z + v.w * v.w;
        dst[2 * c]     = __floats2half2_rn(v.x, v.y);
        dst[2 * c + 1] = __floats2half2_rn(v.z, v.w);
    }
#pragma unroll
    for (int o = 16; o > 0; o >>= 1) s += __shfl_down_sync(0xffffffffu, s, o);
    if (lane == 0) g_b2[row] = s;
}

// ---------------------------------------------------------------------------
// Main kernel: fp16 mma.sync (f16 accum) GEMM + per-(query,split) top-2.
// A (128 x 512 f16) resident in smem; B streamed through 4-stage ring.
// 512 threads, 16 warps (4 m x 4 n), warp tile 32(m) x 32(n).
// 4 warps/SMSP to keep the rt-8 tensor pipe covered through barriers/folds.
// ---------------------------------------------------------------------------
__global__ __launch_bounds__(NT, 1) void knn_mma_kernel() {
    extern __shared__ __align__(1024) char smem[];
    const uint32_t sb = (uint32_t)__cvta_generic_to_shared(smem);
    const int tid    = threadIdx.x;
    const int lane   = tid & 31;
    const int wid    = tid >> 5;
    const int warp_m = wid & 3;
    const int warp_n = wid >> 2;
    const int q0      = blockIdx.x * BM;
    const int split   = blockIdx.y;
    const int n_begin = split * RPS;
    const int n_end   = min(Nn, n_begin + RPS);

    // ---- prologue: b2 tile + resident A ----
    float* sB2 = reinterpret_cast<float*>(smem + SM_B2);
    for (int i = tid; i < TILES * 128; i += NT) {
        int n = n_begin + i;
        sB2[i] = (n < n_end) ? g_b2[n] : FLT_MAX;
    }
#pragma unroll
    for (int it = 0; it < 16; it++) {                 // 8192 granules
        int idx = tid + NT * it;
        int ch = idx >> 10, g = idx & 1023, row = g >> 3, c16 = g & 7;
        const void* src = g_qh + (size_t)(q0 + row) * Dd + ch * BK + c16 * 8;
        cpasync16(sb + SM_A + ch * 16384 + swz128(row * 128 + c16 * 16), src);
    }
    cp_commit();
    cp_wait<0>();
    __syncthreads();

    // B chunk loader: 1024 granules over 512 threads
    auto load_chunk = [&](int c) {
        int t = c >> 3, kc = c & 7, slot = c & 3;
        int n0 = n_begin + t * 128;
        uint32_t bbase = sb + SM_B + slot * 16384;
        const __half* gsrc = g_bh + (size_t)n0 * Dd + kc * BK;
#pragma unroll
        for (int it = 0; it < 2; it++) {
            int g = tid + NT * it;
            int row = g >> 3, c16 = g & 7;
            cpasync16(bbase + swz128(row * 128 + c16 * 16),
                      gsrc + (size_t)row * Dd + c16 * 8);
        }
        cp_commit();
    };

    load_chunk(0); load_chunk(1); load_chunk(2);

    // per-thread top-2 for its 4 query rows
    float v1[4], v2[4];
    int   i1[4], i2[4];
#pragma unroll
    for (int r = 0; r < 4; r++) { v1[r] = FLT_MAX; v2[r] = FLT_MAX; i1[r] = -1; i2[r] = -1; }

    // ldmatrix lane address components
    const uint32_t qq = lane >> 3, l7 = lane & 7;
    const uint32_t a_row = (qq & 1) * 8 + l7;
    const uint32_t a_c   = qq >> 1;
    const uint32_t b_row = (qq >> 1) * 8 + l7;
    const uint32_t b_c   = qq & 1;

    uint32_t acc[2][4][2];          // f16x2 accumulators: [h] = rows r / r+8

#pragma unroll 1
    for (int c = 0; c < CHUNKS; c++) {
        const int t = c >> 3, kc = c & 7, slot = c & 3;

        cp_wait<2>();        // chunk c resident (this thread's part)
        __syncthreads();     // all parts visible; prev consumer done
        if (c + 3 < CHUNKS) load_chunk(c + 3);
        else                cp_commit();      // keep group ledger uniform

        if (kc == 0) {
#pragma unroll
            for (int mt = 0; mt < 2; mt++)
#pragma unroll
                for (int nt = 0; nt < 4; nt++) {
                    acc[mt][nt][0] = 0u; acc[mt][nt][1] = 0u;
                }
        }

        const uint32_t ab = sb + SM_A + kc * 16384;
        const uint32_t bb = sb + SM_B + slot * 16384;
#pragma unroll
        for (int ks = 0; ks < 4; ks++) {
            uint32_t a[2][4];
#pragma unroll
            for (int mt = 0; mt < 2; mt++)
                ldsm4(a[mt][0], a[mt][1], a[mt][2], a[mt][3],
                      ab + swz128((warp_m * 32 + mt * 16 + a_row) * 128 +
                                  (ks * 2 + a_c) * 16));
            uint32_t b[4][2];
#pragma unroll
            for (int ntp = 0; ntp < 2; ntp++) {
                uint32_t r0, r1, r2, r3;
                ldsm4(r0, r1, r2, r3,
                      bb + swz128((warp_n * 32 + ntp * 16 + b_row) * 128 +
                                  (ks * 2 + b_c) * 16));
                b[2 * ntp][0] = r0;     b[2 * ntp][1] = r1;
                b[2 * ntp + 1][0] = r2; b[2 * ntp + 1][1] = r3;
            }
#pragma unroll
            for (int mt = 0; mt < 2; mt++)
#pragma unroll
                for (int nt = 0; nt < 4; nt++)
                    mma_h(acc[mt][nt], a[mt][0], a[mt][1], a[mt][2], a[mt][3],
                          b[nt][0], b[nt][1]);
        }

        if (kc == 7) {
            // fold tile: d2 = b2[n] - 2*dot
            const int colb = warp_n * 32 + 2 * (lane & 3);
            const int ib   = t * 128 + colb;
#pragma unroll
            for (int nt = 0; nt < 4; nt++) {
#pragma unroll
                for (int mt = 0; mt < 2; mt++)
#pragma unroll
                    for (int h = 0; h < 2; h++) {
                        int rr = mt * 2 + h;
                        float2 f = __half22float2(
                            *reinterpret_cast<__half2*>(&acc[mt][nt][h]));
#pragma unroll
                        for (int e = 0; e < 2; e++) {
                            int io = ib + nt * 8 + e;
                            float dot = (e == 0) ? f.x : f.y;
                            float d = fmaf(-2.f, dot, sB2[io]);
                            int n = n_begin + io;
                            if (d < v2[rr]) {
                                if (d < v1[rr]) {
                                    v2[rr] = v1[rr]; i2[rr] = i1[rr];
                                    v1[rr] = d;      i1[rr] = n;
                                } else { v2[rr] = d; i2[rr] = n; }
                            }
                        }
                    }
            }
        }
    }

    // merge top-2 across the 4 lanes of each quad (same query rows), with
    // exact lowest-index tie-breaking
#pragma unroll
    for (int m = 1; m < 4; m <<= 1) {
#pragma unroll
        for (int rr = 0; rr < 4; rr++) {
            float w1 = __shfl_xor_sync(0xffffffffu, v1[rr], m);
            int   j1 = __shfl_xor_sync(0xffffffffu, i1[rr], m);
            float w2 = __shfl_xor_sync(0xffffffffu, v2[rr], m);
            int   j2 = __shfl_xor_sync(0xffffffffu, i2[rr], m);
            if (lex_lt(w1, j1, v1[rr], i1[rr])) {
                float tv = v1[rr]; int ti = i1[rr];
                v1[rr] = w1; i1[rr] = j1; w1 = tv; j1 = ti;
            }
            float s = v2[rr]; int si = i2[rr];
            if (lex_lt(w2, j2, s, si)) { s = w2; si = j2; }
            if (lex_lt(w1, j1, s, si)) { s = w1; si = j1; }
            v2[rr] = s; i2[rr] = si;
        }
    }

    __syncthreads();   // A region reusable now
    float* rv = reinterpret_cast<float*>(smem + SM_A);       // 8 x 128 floats
    int*   ri = reinterpret_cast<int*>(smem + SM_A + 4096);  // 8 x 128 ints
    if ((lane & 3) == 0) {
#pragma unroll
        for (int rr = 0; rr < 4; rr++) {
            int mt = rr >> 1, h = rr & 1;
            int row = warp_m * 32 + mt * 16 + h * 8 + (lane >> 2);
            rv[(warp_n * 2 + 0) * BM + row] = v1[rr];
            rv[(warp_n * 2 + 1) * BM + row] = v2[rr];
            ri[(warp_n * 2 + 0) * BM + row] = i1[rr];
            ri[(warp_n * 2 + 1) * BM + row] = i2[rr];
        }
    }
    __syncthreads();
    if (tid < BM) {
        float a1 = rv[0 * BM + tid], a2 = rv[1 * BM + tid];
        int   x1 = ri[0 * BM + tid], x2 = ri[1 * BM + tid];
#pragma unroll
        for (int g = 1; g < 4; g++) {
            float w1 = rv[(2 * g + 0) * BM + tid], w2 = rv[(2 * g + 1) * BM + tid];
            int   y1 = ri[(2 * g + 0) * BM + tid], y2 = ri[(2 * g + 1) * BM + tid];
            if (lex_lt(w1, y1, a1, x1)) {
                float tv = a1; int ti = x1;
                a1 = w1; x1 = y1; w1 = tv; y1 = ti;
            }
            float s = a2; int si = x2;
            if (lex_lt(w2, y2, s, si)) { s = w2; si = y2; }
            if (lex_lt(w1, y1, s, si)) { s = w1; si = y1; }
            a2 = s; x2 = si;
        }
        g_pv[(2 * split) * Bq + q0 + tid]     = a1;
        g_pi[(2 * split) * Bq + q0 + tid]     = x1;
        g_pv[(2 * split + 1) * Bq + q0 + tid] = a2;
        g_pi[(2 * split + 1) * Bq + q0 + tid] = x2;
    }
}

// ---------------------------------------------------------------------------
// Rescore: exact fp32 d2 for candidates within MARGIN of approx min + gather.
// ---------------------------------------------------------------------------
__global__ void knn_rescore_kernel(const float* __restrict__ Q, const float* __restrict__ Bf,
                                   float* __restrict__ out) {
    const int q = blockIdx.x;
    const int tid = threadIdx.x;
    const int lane = tid & 31;
    const int w = tid >> 5;
    __shared__ float s_v[NCAND];
    __shared__ int   s_i[NCAND];
    __shared__ float s_min, s_best, s_part[4];
    __shared__ int   s_bidx;
    if (tid < NCAND) { s_v[tid] = g_pv[tid * Bq + q]; s_i[tid] = g_pi[tid * Bq + q]; }
    if (tid == 0) { s_best = FLT_MAX; s_bidx = 0x7fffffff; }
    __syncthreads();
    if (tid == 0) {
        float m = FLT_MAX;
        for (int c = 0; c < NCAND; c++) m = fminf(m, s_v[c]);
        s_min = m;
    }
    __syncthreads();
    float4 q4 = reinterpret_cast<const float4*>(Q + (size_t)q * Dd)[tid];
    for (int c = 0; c < NCAND; c++) {
        float vc = s_v[c]; int ic = s_i[c];
        if (ic >= 0 && vc <= s_min + MARGIN) {        // uniform across block
            float4 b4 = reinterpret_cast<const float4*>(Bf + (size_t)ic * Dd)[tid];
            float p = q4.x * b4.x + q4.y * b4.y + q4.z * b4.z + q4.w * b4.w;
#pragma unroll
            for (int o = 16; o > 0; o >>= 1) p += __shfl_down_sync(0xffffffffu, p, o);
            if (lane == 0) s_part[w] = p;
            __syncthreads();
            if (tid == 0) {
                float dot = s_part[0] + s_part[1] + s_part[2] + s_part[3];
                float d = g_b2[ic] - 2.f * dot;
                if (d < s_best || (d == s_best && ic < s_bidx)) { s_best = d; s_bidx = ic; }
            }
            __syncthreads();
        }
    }
    __syncthreads();
    int bi = s_bidx;
    reinterpret_cast<float4*>(out + (size_t)q * Dd)[tid] =
        reinterpret_cast<const float4*>(Bf + (size_t)bi * Dd)[tid];
}

// ---------------------------------------------------------------------------
extern "C" void kernel_launch(void* const* d_in, const int* in_sizes, int n_in,
                              void* d_out, int out_size) {
    const float* Q  = (const float*)d_in[0];   // [2048, 512]
    const float* Bf = (const float*)d_in[1];   // [100000, 512]
    float* out = (float*)d_out;                // [2048, 512]

    cudaFuncSetAttribute(knn_mma_kernel,
                         cudaFuncAttributeMaxDynamicSharedMemorySize, SMEM_TOTAL);

    knn_convq_kernel<<<(Bq * Dd / 4) / 256, 256>>>(Q);
    knn_convb_kernel<<<(Nn + 7) / 8, 256>>>(Bf);
    dim3 grid(Bq / BM, NSPLIT);
    knn_mma_kernel<<<grid, NT, SMEM_TOTAL>>>();
    knn_rescore_kernel<<<Bq, 128>>>(Q, Bf, out);
}

// round 9
// speedup vs baseline: 1.1299x; 1.1299x over previous
#include <cuda_runtime.h>
#include <cuda_fp16.h>
#include <cfloat>
#include <cstdint>

#define Bq 2048
#define Nn 100000
#define Dd 512
#define BM 128
#define BN 128
#define BK 64                    // fp16 k-chunk (64 elts = 128 B = SW128 row)
#define NSPLIT 37
#define RPS 2703                 // ceil(Nn / NSPLIT)
#define NCAND (2 * NSPLIT)
#define MARGIN 2.0f

#define TILES 22                 // ceil(RPS / 128)
#define KCH   8                  // k-chunks per tile (512/64)
#define CHUNKS (TILES * KCH)     // 176
#define STAGES 4

// dynamic smem layout (bytes)
#define SM_B2 0                              // TILES*128 floats = 11264
#define SM_A  12288                          // 8 chunks x 16384 = 131072 (resident)
#define SM_B  (SM_A + KCH * 16384)           // 4-stage ring x 16384
#define SMEM_TOTAL (SM_B + STAGES * 16384)   // 208896

// ---- device-global scratch (no allocs; zero-initialized) ----
__device__ __half g_qh[Bq * Dd];                  // 2 MB
__device__ __half g_bh[(Nn + 256) * Dd];          // ~102 MB (pad rows stay 0)
__device__ float g_b2[Nn];
__device__ float g_pv[NCAND * Bq];
__device__ int   g_pi[NCAND * Bq];

// ---------------------------------------------------------------------------
// helpers
// ---------------------------------------------------------------------------
__device__ __forceinline__ uint32_t swz128(uint32_t off) {   // SW128 swizzle
    return off ^ ((off >> 3) & 0x70u);
}
__device__ __forceinline__ void cpasync16(uint32_t dst, const void* src) {
    asm volatile("cp.async.cg.shared.global [%0], [%1], 16;" :: "r"(dst), "l"(src));
}
__device__ __forceinline__ void cp_commit() { asm volatile("cp.async.commit_group;"); }
template <int N>
__device__ __forceinline__ void cp_wait() { asm volatile("cp.async.wait_group %0;" :: "n"(N)); }
__device__ __forceinline__ void ldsm4(uint32_t& r0, uint32_t& r1, uint32_t& r2, uint32_t& r3,
                                      uint32_t a) {
    asm volatile("ldmatrix.sync.aligned.m8n8.x4.shared.b16 {%0,%1,%2,%3}, [%4];"
                 : "=r"(r0), "=r"(r1), "=r"(r2), "=r"(r3) : "r"(a));
}
// fp16 inputs, fp16 accumulators: D(2 x f16x2) = A(4) * B(2) + D
__device__ __forceinline__ void mma_h(uint32_t c[2], uint32_t a0, uint32_t a1, uint32_t a2,
                                      uint32_t a3, uint32_t b0, uint32_t b1) {
    asm volatile(
        "mma.sync.aligned.m16n8k16.row.col.f16.f16.f16.f16 "
        "{%0,%1},{%2,%3,%4,%5},{%6,%7},{%0,%1};"
        : "+r"(c[0]), "+r"(c[1])
        : "r"(a0), "r"(a1), "r"(a2), "r"(a3), "r"(b0), "r"(b1));
}
// lexicographic (value, index) less-than
__device__ __forceinline__ bool lex_lt(float a, int ia, float b, int ib) {
    return (a < b) || (a == b && ia < ib);
}

// ---------------------------------------------------------------------------
// Convert kernels: fp32 -> fp16 (convb also computes exact fp32 b2)
// ---------------------------------------------------------------------------
__global__ void knn_convq_kernel(const float* __restrict__ Q) {
    int i = blockIdx.x * 256 + threadIdx.x;      // float4 index
    float4 v = reinterpret_cast<const float4*>(Q)[i];
    __half2* dst = reinterpret_cast<__half2*>(g_qh);
    dst[2 * i]     = __floats2half2_rn(v.x, v.y);
    dst[2 * i + 1] = __floats2half2_rn(v.z, v.w);
}

__global__ void knn_convb_kernel(const float* __restrict__ Bf) {
    int warp = threadIdx.x >> 5, lane = threadIdx.x & 31;
    int row = blockIdx.x * 8 + warp;
    if (row >= Nn) return;
    const float4* src = reinterpret_cast<const float4*>(Bf + (size_t)row * Dd);
    __half2* dst = reinterpret_cast<__half2*>(g_bh + (size_t)row * Dd);
    float s = 0.f;
#pragma unroll
    for (int it = 0; it < 4; it++) {
        int c = lane + 32 * it;
        float4 v = src[c];
        s += v.x * v.x + v.y * v.y + v.z * v.z + v.w * v.w;
        dst[2 * c]     = __floats2half2_rn(v.x, v.y);
        dst[2 * c + 1] = __floats2half2_rn(v.z, v.w);
    }
#pragma unroll
    for (int o = 16; o > 0; o >>= 1) s += __shfl_down_sync(0xffffffffu, s, o);
    if (lane == 0) g_b2[row] = s;
}

// ---------------------------------------------------------------------------
// Main kernel: fp16 mma.sync (f16 accum) GEMM + per-(query,split) top-2.
// A (128 x 512 f16) resident in smem; B streamed through 4-stage ring.
// 256 threads, 8 warps (4 m x 2 n), warp tile 32(m) x 64(n).
// Intra-chunk fragment double-buffering: LDSM for k-slice ks+1 issues while
// the MMAs of slice ks occupy the tensor pipe.
// ---------------------------------------------------------------------------
__global__ __launch_bounds__(256, 1) void knn_mma_kernel() {
    extern __shared__ __align__(1024) char smem[];
    const uint32_t sb = (uint32_t)__cvta_generic_to_shared(smem);
    const int tid    = threadIdx.x;
    const int lane   = tid & 31;
    const int wid    = tid >> 5;
    const int warp_m = wid >> 1;
    const int warp_n = wid & 1;
    const int q0      = blockIdx.x * BM;
    const int split   = blockIdx.y;
    const int n_begin = split * RPS;
    const int n_end   = min(Nn, n_begin + RPS);

    // ---- prologue: b2 tile + resident A ----
    float* sB2 = reinterpret_cast<float*>(smem + SM_B2);
    for (int i = tid; i < TILES * 128; i += 256) {
        int n = n_begin + i;
        sB2[i] = (n < n_end) ? g_b2[n] : FLT_MAX;
    }
#pragma unroll
    for (int it = 0; it < 32; it++) {                 // 8192 granules
        int idx = tid + 256 * it;
        int ch = idx >> 10, g = idx & 1023, row = g >> 3, c16 = g & 7;
        const void* src = g_qh + (size_t)(q0 + row) * Dd + ch * BK + c16 * 8;
        cpasync16(sb + SM_A + ch * 16384 + swz128(row * 128 + c16 * 16), src);
    }
    cp_commit();
    cp_wait<0>();
    __syncthreads();

    // B chunk loader: 1024 granules over 256 threads
    auto load_chunk = [&](int c) {
        int t = c >> 3, kc = c & 7, slot = c & 3;
        int n0 = n_begin + t * 128;
        uint32_t bbase = sb + SM_B + slot * 16384;
        const __half* gsrc = g_bh + (size_t)n0 * Dd + kc * BK;
#pragma unroll
        for (int it = 0; it < 4; it++) {
            int g = tid + 256 * it;
            int row = g >> 3, c16 = g & 7;
            cpasync16(bbase + swz128(row * 128 + c16 * 16),
                      gsrc + (size_t)row * Dd + c16 * 8);
        }
        cp_commit();
    };

    load_chunk(0); load_chunk(1); load_chunk(2);

    // per-thread top-2 for its 4 query rows
    float v1[4], v2[4];
    int   i1[4], i2[4];
#pragma unroll
    for (int r = 0; r < 4; r++) { v1[r] = FLT_MAX; v2[r] = FLT_MAX; i1[r] = -1; i2[r] = -1; }

    // ldmatrix lane address components
    const uint32_t qq = lane >> 3, l7 = lane & 7;
    const uint32_t a_row = (qq & 1) * 8 + l7;
    const uint32_t a_c   = qq >> 1;
    const uint32_t b_row = (qq >> 1) * 8 + l7;
    const uint32_t b_c   = qq & 1;

    uint32_t acc[2][8][2];          // f16x2 accumulators: [h] = rows r / r+8

    // double-buffered fragments
    uint32_t afr[2][2][4];          // [buf][mt][reg]
    uint32_t bfr[2][8][2];          // [buf][nt][reg]

    auto load_frags = [&](uint32_t ab, uint32_t bb, int ks, int buf) {
#pragma unroll
        for (int mt = 0; mt < 2; mt++)
            ldsm4(afr[buf][mt][0], afr[buf][mt][1], afr[buf][mt][2], afr[buf][mt][3],
                  ab + swz128((warp_m * 32 + mt * 16 + a_row) * 128 +
                              (ks * 2 + a_c) * 16));
#pragma unroll
        for (int ntp = 0; ntp < 4; ntp++) {
            uint32_t r0, r1, r2, r3;
            ldsm4(r0, r1, r2, r3,
                  bb + swz128((warp_n * 64 + ntp * 16 + b_row) * 128 +
                              (ks * 2 + b_c) * 16));
            bfr[buf][2 * ntp][0] = r0;     bfr[buf][2 * ntp][1] = r1;
            bfr[buf][2 * ntp + 1][0] = r2; bfr[buf][2 * ntp + 1][1] = r3;
        }
    };

#pragma unroll 1
    for (int c = 0; c < CHUNKS; c++) {
        const int t = c >> 3, kc = c & 7, slot = c & 3;

        cp_wait<2>();        // chunk c resident (this thread's part)
        __syncthreads();     // all parts visible; prev consumer done

        const uint32_t ab = sb + SM_A + kc * 16384;
        const uint32_t bb = sb + SM_B + slot * 16384;

        load_frags(ab, bb, 0, 0);              // prime slice 0

        if (c + 3 < CHUNKS) load_chunk(c + 3);
        else                cp_commit();       // keep group ledger uniform

        if (kc == 0) {
#pragma unroll
            for (int mt = 0; mt < 2; mt++)
#pragma unroll
                for (int nt = 0; nt < 8; nt++) {
                    acc[mt][nt][0] = 0u; acc[mt][nt][1] = 0u;
                }
        }

#pragma unroll
        for (int ks = 0; ks < 4; ks++) {
            const int buf = ks & 1;
            if (ks < 3) load_frags(ab, bb, ks + 1, buf ^ 1);   // overlap w/ MMAs
#pragma unroll
            for (int mt = 0; mt < 2; mt++)
#pragma unroll
                for (int nt = 0; nt < 8; nt++)
                    mma_h(acc[mt][nt], afr[buf][mt][0], afr[buf][mt][1],
                          afr[buf][mt][2], afr[buf][mt][3],
                          bfr[buf][nt][0], bfr[buf][nt][1]);
        }

        if (kc == 7) {
            // fold tile: d2 = b2[n] - 2*dot
            const int colb = warp_n * 64 + 2 * (lane & 3);
            const int ib   = t * 128 + colb;
#pragma unroll
            for (int nt = 0; nt < 8; nt++) {
#pragma unroll
                for (int mt = 0; mt < 2; mt++)
#pragma unroll
                    for (int h = 0; h < 2; h++) {
                        int rr = mt * 2 + h;
                        float2 f = __half22float2(
                            *reinterpret_cast<__half2*>(&acc[mt][nt][h]));
#pragma unroll
                        for (int e = 0; e < 2; e++) {
                            int io = ib + nt * 8 + e;
                            float dot = (e == 0) ? f.x : f.y;
                            float d = fmaf(-2.f, dot, sB2[io]);
                            int n = n_begin + io;
                            if (d < v2[rr]) {
                                if (d < v1[rr]) {
                                    v2[rr] = v1[rr]; i2[rr] = i1[rr];
                                    v1[rr] = d;      i1[rr] = n;
                                } else { v2[rr] = d; i2[rr] = n; }
                            }
                        }
                    }
            }
        }
    }

    // merge top-2 across the 4 lanes of each quad (same query rows), with
    // exact lowest-index tie-breaking
#pragma unroll
    for (int m = 1; m < 4; m <<= 1) {
#pragma unroll
        for (int rr = 0; rr < 4; rr++) {
            float w1 = __shfl_xor_sync(0xffffffffu, v1[rr], m);
            int   j1 = __shfl_xor_sync(0xffffffffu, i1[rr], m);
            float w2 = __shfl_xor_sync(0xffffffffu, v2[rr], m);
            int   j2 = __shfl_xor_sync(0xffffffffu, i2[rr], m);
            if (lex_lt(w1, j1, v1[rr], i1[rr])) {
                float tv = v1[rr]; int ti = i1[rr];
                v1[rr] = w1; i1[rr] = j1; w1 = tv; j1 = ti;
            }
            float s = v2[rr]; int si = i2[rr];
            if (lex_lt(w2, j2, s, si)) { s = w2; si = j2; }
            if (lex_lt(w1, j1, s, si)) { s = w1; si = j1; }
            v2[rr] = s; i2[rr] = si;
        }
    }

    __syncthreads();   // A region reusable now
    float* rv = reinterpret_cast<float*>(smem + SM_A);       // 4 x 128 floats
    int*   ri = reinterpret_cast<int*>(smem + SM_A + 2048);  // 4 x 128 ints
    if ((lane & 3) == 0) {
#pragma unroll
        for (int rr = 0; rr < 4; rr++) {
            int mt = rr >> 1, h = rr & 1;
            int row = warp_m * 32 + mt * 16 + h * 8 + (lane >> 2);
            rv[(warp_n * 2 + 0) * BM + row] = v1[rr];
            rv[(warp_n * 2 + 1) * BM + row] = v2[rr];
            ri[(warp_n * 2 + 0) * BM + row] = i1[rr];
            ri[(warp_n * 2 + 1) * BM + row] = i2[rr];
        }
    }
    __syncthreads();
    if (tid < BM) {
        float a1 = rv[0 * BM + tid], a2 = rv[1 * BM + tid];
        int   x1 = ri[0 * BM + tid], x2 = ri[1 * BM + tid];
        float w1 = rv[2 * BM + tid], w2 = rv[3 * BM + tid];
        int   y1 = ri[2 * BM + tid], y2 = ri[3 * BM + tid];
        if (lex_lt(w1, y1, a1, x1)) {
            float tv = a1; int ti = x1;
            a1 = w1; x1 = y1; w1 = tv; y1 = ti;
        }
        float s = a2; int si = x2;
        if (lex_lt(w2, y2, s, si)) { s = w2; si = y2; }
        if (lex_lt(w1, y1, s, si)) { s = w1; si = y1; }
        g_pv[(2 * split) * Bq + q0 + tid]     = a1;
        g_pi[(2 * split) * Bq + q0 + tid]     = x1;
        g_pv[(2 * split + 1) * Bq + q0 + tid] = s;
        g_pi[(2 * split + 1) * Bq + q0 + tid] = si;
    }
}

// ---------------------------------------------------------------------------
// Rescore: exact fp32 d2 for candidates within MARGIN of approx min + gather.
// ---------------------------------------------------------------------------
__global__ void knn_rescore_kernel(const float* __restrict__ Q, const float* __restrict__ Bf,
                                   float* __restrict__ out) {
    const int q = blockIdx.x;
    const int tid = threadIdx.x;
    const int lane = tid & 31;
    const int w = tid >> 5;
    __shared__ float s_v[NCAND];
    __shared__ int   s_i[NCAND];
    __shared__ float s_min, s_best, s_part[4];
    __shared__ int   s_bidx;
    if (tid < NCAND) { s_v[tid] = g_pv[tid * Bq + q]; s_i[tid] = g_pi[tid * Bq + q]; }
    if (tid == 0) { s_best = FLT_MAX; s_bidx = 0x7fffffff; }
    __syncthreads();
    if (tid == 0) {
        float m = FLT_MAX;
        for (int c = 0; c < NCAND; c++) m = fminf(m, s_v[c]);
        s_min = m;
    }
    __syncthreads();
    float4 q4 = reinterpret_cast<const float4*>(Q + (size_t)q * Dd)[tid];
    for (int c = 0; c < NCAND; c++) {
        float vc = s_v[c]; int ic = s_i[c];
        if (ic >= 0 && vc <= s_min + MARGIN) {        // uniform across block
            float4 b4 = reinterpret_cast<const float4*>(Bf + (size_t)ic * Dd)[tid];
            float p = q4.x * b4.x + q4.y * b4.y + q4.z * b4.z + q4.w * b4.w;
#pragma unroll
            for (int o = 16; o > 0; o >>= 1) p += __shfl_down_sync(0xffffffffu, p, o);
            if (lane == 0) s_part[w] = p;
            __syncthreads();
            if (tid == 0) {
                float dot = s_part[0] + s_part[1] + s_part[2] + s_part[3];
                float d = g_b2[ic] - 2.f * dot;
                if (d < s_best || (d == s_best && ic < s_bidx)) { s_best = d; s_bidx = ic; }
            }
            __syncthreads();
        }
    }
    __syncthreads();
    int bi = s_bidx;
    reinterpret_cast<float4*>(out + (size_t)q * Dd)[tid] =
        reinterpret_cast<const float4*>(Bf + (size_t)bi * Dd)[tid];
}

// ---------------------------------------------------------------------------
extern "C" void kernel_launch(void* const* d_in, const int* in_sizes, int n_in,
                              void* d_out, int out_size) {
    const float* Q  = (const float*)d_in[0];   // [2048, 512]
    const float* Bf = (const float*)d_in[1];   // [100000, 512]
    float* out = (float*)d_out;                // [2048, 512]

    cudaFuncSetAttribute(knn_mma_kernel,
                         cudaFuncAttributeMaxDynamicSharedMemorySize, SMEM_TOTAL);

    knn_convq_kernel<<<(Bq * Dd / 4) / 256, 256>>>(Q);
    knn_convb_kernel<<<(Nn + 7) / 8, 256>>>(Bf);
    dim3 grid(Bq / BM, NSPLIT);
    knn_mma_kernel<<<grid, 256, SMEM_TOTAL>>>();
    knn_rescore_kernel<<<Bq, 128>>>(Q, Bf, out);
}

// round 11
// speedup vs baseline: 1.1812x; 1.0454x over previous
#include <cuda_runtime.h>
#include <cuda_fp16.h>
#include <cfloat>
#include <cstdint>

#define Bq 2048
#define Nn 100000
#define Dd 512
#define BM 128
#define BN 128
#define BK 64                    // fp16 k-chunk (64 elts = 128 B = SW128 row)
#define NSPLIT 37
#define RPS 2703                 // ceil(Nn / NSPLIT)
#define NCAND (2 * NSPLIT)
#define MARGIN 2.0f
#define NT 288                   // 8 consumer warps + 1 producer warp

#define TILES 22                 // ceil(RPS / 128)
#define KCH   8                  // k-chunks per tile (512/64)
#define CHUNKS (TILES * KCH)     // 176
#define STAGES 4

// dynamic smem layout (bytes)
#define SM_B2 0                              // TILES*128 floats = 11264
#define SM_MB 11264                          // full[4]@0, empty[4]@32 (64 B)
#define SM_A  12288                          // 8 chunks x 16384 = 131072 (resident)
#define SM_B  (SM_A + KCH * 16384)           // 4-stage ring x 16384
#define SM_RED (SM_B + STAGES * 16384)       // 4 KB reduction stash
#define SMEM_TOTAL (SM_RED + 4096)           // 212992

// ---- device-global scratch (no allocs; zero-initialized) ----
__device__ __half g_qh[Bq * Dd];                  // 2 MB
__device__ __half g_bh[(Nn + 256) * Dd];          // ~102 MB (pad rows stay 0)
__device__ float g_b2[Nn];
__device__ float g_pv[NCAND * Bq];
__device__ int   g_pi[NCAND * Bq];

// ---------------------------------------------------------------------------
// helpers
// ---------------------------------------------------------------------------
__device__ __forceinline__ uint32_t swz128(uint32_t off) {   // SW128 swizzle
    return off ^ ((off >> 3) & 0x70u);
}
__device__ __forceinline__ void cpasync16(uint32_t dst, const void* src) {
    asm volatile("cp.async.cg.shared.global [%0], [%1], 16;" :: "r"(dst), "l"(src));
}
__device__ __forceinline__ void cp_commit() { asm volatile("cp.async.commit_group;"); }
template <int N>
__device__ __forceinline__ void cp_wait() { asm volatile("cp.async.wait_group %0;" :: "n"(N)); }
// .noinc: barrier count pre-includes our 32 arrivals; do NOT self-register.
__device__ __forceinline__ void cp_mbar_arrive_noinc(uint32_t mbar) {
    asm volatile("cp.async.mbarrier.arrive.noinc.shared.b64 [%0];" :: "r"(mbar) : "memory");
}
__device__ __forceinline__ void mbar_init(uint32_t a, uint32_t cnt) {
    asm volatile("mbarrier.init.shared.b64 [%0], %1;" :: "r"(a), "r"(cnt) : "memory");
}
__device__ __forceinline__ void mbar_arrive(uint32_t a) {
    asm volatile("mbarrier.arrive.release.cta.shared::cta.b64 _, [%0];"
                 :: "r"(a) : "memory");
}
__device__ __forceinline__ void mbar_wait(uint32_t a, uint32_t ph) {
    asm volatile(
        "{\n\t.reg .pred P;\n\t"
        "W%=:\n\t"
        "mbarrier.try_wait.parity.acquire.cta.shared::cta.b64 P, [%0], %1;\n\t"
        "@P bra D%=;\n\t"
        "bra W%=;\n\t"
        "D%=:\n\t}"
        :: "r"(a), "r"(ph) : "memory");
}
__device__ __forceinline__ void ldsm4(uint32_t& r0, uint32_t& r1, uint32_t& r2, uint32_t& r3,
                                      uint32_t a) {
    asm volatile("ldmatrix.sync.aligned.m8n8.x4.shared.b16 {%0,%1,%2,%3}, [%4];"
                 : "=r"(r0), "=r"(r1), "=r"(r2), "=r"(r3) : "r"(a));
}
// fp16 inputs, fp16 accumulators: D(2 x f16x2) = A(4) * B(2) + D
__device__ __forceinline__ void mma_h(uint32_t c[2], uint32_t a0, uint32_t a1, uint32_t a2,
                                      uint32_t a3, uint32_t b0, uint32_t b1) {
    asm volatile(
        "mma.sync.aligned.m16n8k16.row.col.f16.f16.f16.f16 "
        "{%0,%1},{%2,%3,%4,%5},{%6,%7},{%0,%1};"
        : "+r"(c[0]), "+r"(c[1])
        : "r"(a0), "r"(a1), "r"(a2), "r"(a3), "r"(b0), "r"(b1));
}
// lexicographic (value, index) less-than
__device__ __forceinline__ bool lex_lt(float a, int ia, float b, int ib) {
    return (a < b) || (a == b && ia < ib);
}

// ---------------------------------------------------------------------------
// Convert kernels: fp32 -> fp16 (convb also computes exact fp32 b2)
// ---------------------------------------------------------------------------
__global__ void knn_convq_kernel(const float* __restrict__ Q) {
    int i = blockIdx.x * 256 + threadIdx.x;      // float4 index
    float4 v = reinterpret_cast<const float4*>(Q)[i];
    __half2* dst = reinterpret_cast<__half2*>(g_qh);
    dst[2 * i]     = __floats2half2_rn(v.x, v.y);
    dst[2 * i + 1] = __floats2half2_rn(v.z, v.w);
}

__global__ void knn_convb_kernel(const float* __restrict__ Bf) {
    int warp = threadIdx.x >> 5, lane = threadIdx.x & 31;
    int row = blockIdx.x * 8 + warp;
    if (row >= Nn) return;
    const float4* src = reinterpret_cast<const float4*>(Bf + (size_t)row * Dd);
    __half2* dst = reinterpret_cast<__half2*>(g_bh + (size_t)row * Dd);
    float s = 0.f;
#pragma unroll
    for (int it = 0; it < 4; it++) {
        int c = lane + 32 * it;
        float4 v = src[c];
        s += v.x * v.x + v.y * v.y + v.z * v.z + v.w * v.w;
        dst[2 * c]     = __floats2half2_rn(v.x, v.y);
        dst[2 * c + 1] = __floats2half2_rn(v.z, v.w);
    }
#pragma unroll
    for (int o = 16; o > 0; o >>= 1) s += __shfl_down_sync(0xffffffffu, s, o);
    if (lane == 0) g_b2[row] = s;
}

// ---------------------------------------------------------------------------
// Main kernel: fp16 mma.sync (f16 accum) GEMM + per-(query,split) top-2.
// Warp-specialized: warps 0-7 consume (LDSM+MMA+fold), warp 8 produces
// (cp.async B ring). No block-wide barrier in the mainloop — mbarrier ring
// of 4 stages, cp.async.mbarrier.arrive.noinc completion signalling.
// ---------------------------------------------------------------------------
__global__ __launch_bounds__(NT, 1) void knn_mma_kernel() {
    extern __shared__ __align__(1024) char smem[];
    const uint32_t sb = (uint32_t)__cvta_generic_to_shared(smem);
    const int tid    = threadIdx.x;
    const int lane   = tid & 31;
    const int wid    = tid >> 5;
    const int q0      = blockIdx.x * BM;
    const int split   = blockIdx.y;
    const int n_begin = split * RPS;
    const int n_end   = min(Nn, n_begin + RPS);

    const uint32_t mb_full  = sb + SM_MB;        // 4 x 8B, arrive count 32
    const uint32_t mb_empty = sb + SM_MB + 32;   // 4 x 8B, arrive count 256

    if (tid == 0) {
#pragma unroll
        for (int s = 0; s < STAGES; s++) {
            mbar_init(mb_full + 8 * s, 32);
            mbar_init(mb_empty + 8 * s, 256);
        }
    }

    // ---- prologue: b2 tile + resident A (all 288 threads) ----
    float* sB2 = reinterpret_cast<float*>(smem + SM_B2);
    for (int i = tid; i < TILES * 128; i += NT) {
        int n = n_begin + i;
        sB2[i] = (n < n_end) ? g_b2[n] : FLT_MAX;
    }
    for (int idx = tid; idx < 8192; idx += NT) {       // 8192 16B granules
        int ch = idx >> 10, g = idx & 1023, row = g >> 3, c16 = g & 7;
        const void* src = g_qh + (size_t)(q0 + row) * Dd + ch * BK + c16 * 8;
        cpasync16(sb + SM_A + ch * 16384 + swz128(row * 128 + c16 * 16), src);
    }
    cp_commit();
    cp_wait<0>();
    __syncthreads();     // A + b2 + mbarriers visible to everyone

    if (wid == 8) {
        // ================= producer (warp 8) =================
#pragma unroll 1
        for (int c = 0; c < CHUNKS; c++) {
            const int t = c >> 3, kc = c & 7, slot = c & 3;
            if (c >= STAGES) mbar_wait(mb_empty + 8 * slot, ((c >> 2) - 1) & 1);
            const __half* gsrc = g_bh + (size_t)(n_begin + t * 128) * Dd + kc * BK;
            const uint32_t bbase = sb + SM_B + slot * 16384;
#pragma unroll
            for (int it = 0; it < 32; it++) {
                int g = lane + 32 * it;
                int row = g >> 3, c16 = g & 7;
                cpasync16(bbase + swz128(row * 128 + c16 * 16),
                          gsrc + (size_t)row * Dd + c16 * 8);
            }
            cp_mbar_arrive_noinc(mb_full + 8 * slot);  // 32 pre-counted arrivals
        }
    } else {
        // ================= consumers (warps 0-7) =================
        const int warp_m = wid >> 1;
        const int warp_n = wid & 1;

        // per-thread top-2 for its 4 query rows
        float v1[4], v2[4];
        int   i1[4], i2[4];
#pragma unroll
        for (int r = 0; r < 4; r++) { v1[r] = FLT_MAX; v2[r] = FLT_MAX; i1[r] = -1; i2[r] = -1; }

        // ldmatrix lane address components
        const uint32_t qq = lane >> 3, l7 = lane & 7;
        const uint32_t a_row = (qq & 1) * 8 + l7;
        const uint32_t a_c   = qq >> 1;
        const uint32_t b_row = (qq >> 1) * 8 + l7;
        const uint32_t b_c   = qq & 1;

        uint32_t acc[2][8][2];          // f16x2 accumulators
        uint32_t afr[2][2][4];          // [buf][mt][reg]
        uint32_t bfr[2][8][2];          // [buf][nt][reg]

        auto load_frags = [&](uint32_t ab, uint32_t bb, int ks, int buf) {
#pragma unroll
            for (int mt = 0; mt < 2; mt++)
                ldsm4(afr[buf][mt][0], afr[buf][mt][1], afr[buf][mt][2], afr[buf][mt][3],
                      ab + swz128((warp_m * 32 + mt * 16 + a_row) * 128 +
                                  (ks * 2 + a_c) * 16));
#pragma unroll
            for (int ntp = 0; ntp < 4; ntp++) {
                uint32_t r0, r1, r2, r3;
                ldsm4(r0, r1, r2, r3,
                      bb + swz128((warp_n * 64 + ntp * 16 + b_row) * 128 +
                                  (ks * 2 + b_c) * 16));
                bfr[buf][2 * ntp][0] = r0;     bfr[buf][2 * ntp][1] = r1;
                bfr[buf][2 * ntp + 1][0] = r2; bfr[buf][2 * ntp + 1][1] = r3;
            }
        };

#pragma unroll 1
        for (int c = 0; c < CHUNKS; c++) {
            const int t = c >> 3, kc = c & 7, slot = c & 3;

            mbar_wait(mb_full + 8 * slot, (c >> 2) & 1);   // B chunk ready

            const uint32_t ab = sb + SM_A + kc * 16384;
            const uint32_t bb = sb + SM_B + slot * 16384;

            if (kc == 0) {
#pragma unroll
                for (int mt = 0; mt < 2; mt++)
#pragma unroll
                    for (int nt = 0; nt < 8; nt++) {
                        acc[mt][nt][0] = 0u; acc[mt][nt][1] = 0u;
                    }
            }

            load_frags(ab, bb, 0, 0);
#pragma unroll
            for (int ks = 0; ks < 4; ks++) {
                const int buf = ks & 1;
                if (ks < 3) load_frags(ab, bb, ks + 1, buf ^ 1);
#pragma unroll
                for (int mt = 0; mt < 2; mt++)
#pragma unroll
                    for (int nt = 0; nt < 8; nt++)
                        mma_h(acc[mt][nt], afr[buf][mt][0], afr[buf][mt][1],
                              afr[buf][mt][2], afr[buf][mt][3],
                              bfr[buf][nt][0], bfr[buf][nt][1]);
            }

            mbar_arrive(mb_empty + 8 * slot);   // stage free; fold below only
                                                // touches registers + sB2

            if (kc == 7) {
                const int colb = warp_n * 64 + 2 * (lane & 3);
                const int ib   = t * 128 + colb;
#pragma unroll
                for (int nt = 0; nt < 8; nt++) {
#pragma unroll
                    for (int mt = 0; mt < 2; mt++)
#pragma unroll
                        for (int h = 0; h < 2; h++) {
                            int rr = mt * 2 + h;
                            float2 f = __half22float2(
                                *reinterpret_cast<__half2*>(&acc[mt][nt][h]));
#pragma unroll
                            for (int e = 0; e < 2; e++) {
                                int io = ib + nt * 8 + e;
                                float dot = (e == 0) ? f.x : f.y;
                                float d = fmaf(-2.f, dot, sB2[io]);
                                int n = n_begin + io;
                                if (d < v2[rr]) {
                                    if (d < v1[rr]) {
                                        v2[rr] = v1[rr]; i2[rr] = i1[rr];
                                        v1[rr] = d;      i1[rr] = n;
                                    } else { v2[rr] = d; i2[rr] = n; }
                                }
                            }
                        }
                }
            }
        }

        // merge top-2 across the 4 lanes of each quad, lowest-index ties
#pragma unroll
        for (int m = 1; m < 4; m <<= 1) {
#pragma unroll
            for (int rr = 0; rr < 4; rr++) {
                float w1 = __shfl_xor_sync(0xffffffffu, v1[rr], m);
                int   j1 = __shfl_xor_sync(0xffffffffu, i1[rr], m);
                float w2 = __shfl_xor_sync(0xffffffffu, v2[rr], m);
                int   j2 = __shfl_xor_sync(0xffffffffu, i2[rr], m);
                if (lex_lt(w1, j1, v1[rr], i1[rr])) {
                    float tv = v1[rr]; int ti = i1[rr];
                    v1[rr] = w1; i1[rr] = j1; w1 = tv; j1 = ti;
                }
                float s = v2[rr]; int si = i2[rr];
                if (lex_lt(w2, j2, s, si)) { s = w2; si = j2; }
                if (lex_lt(w1, j1, s, si)) { s = w1; si = j1; }
                v2[rr] = s; i2[rr] = si;
            }
        }

        // stash into DEDICATED region (no overlap with A/B still in use by
        // laggard warps)
        float* rv = reinterpret_cast<float*>(smem + SM_RED);       // 4 x 128 f
        int*   ri = reinterpret_cast<int*>(smem + SM_RED + 2048);  // 4 x 128 i
        if ((lane & 3) == 0) {
#pragma unroll
            for (int rr = 0; rr < 4; rr++) {
                int mt = rr >> 1, h = rr & 1;
                int row = warp_m * 32 + mt * 16 + h * 8 + (lane >> 2);
                rv[(warp_n * 2 + 0) * BM + row] = v1[rr];
                rv[(warp_n * 2 + 1) * BM + row] = v2[rr];
                ri[(warp_n * 2 + 0) * BM + row] = i1[rr];
                ri[(warp_n * 2 + 1) * BM + row] = i2[rr];
            }
        }
    }

    __syncthreads();     // all consumer stashes visible
    if (tid < BM) {
        float* rv = reinterpret_cast<float*>(smem + SM_RED);
        int*   ri = reinterpret_cast<int*>(smem + SM_RED + 2048);
        float a1 = rv[0 * BM + tid], a2 = rv[1 * BM + tid];
        int   x1 = ri[0 * BM + tid], x2 = ri[1 * BM + tid];
        float w1 = rv[2 * BM + tid], w2 = rv[3 * BM + tid];
        int   y1 = ri[2 * BM + tid], y2 = ri[3 * BM + tid];
        if (lex_lt(w1, y1, a1, x1)) {
            float tv = a1; int ti = x1;
            a1 = w1; x1 = y1; w1 = tv; y1 = ti;
        }
        float s = a2; int si = x2;
        if (lex_lt(w2, y2, s, si)) { s = w2; si = y2; }
        if (lex_lt(w1, y1, s, si)) { s = w1; si = y1; }
        g_pv[(2 * split) * Bq + q0 + tid]     = a1;
        g_pi[(2 * split) * Bq + q0 + tid]     = x1;
        g_pv[(2 * split + 1) * Bq + q0 + tid] = s;
        g_pi[(2 * split + 1) * Bq + q0 + tid] = si;
    }
}

// ---------------------------------------------------------------------------
// Rescore: exact fp32 d2 for candidates within MARGIN of approx min + gather.
// ---------------------------------------------------------------------------
__global__ void knn_rescore_kernel(const float* __restrict__ Q, const float* __restrict__ Bf,
                                   float* __restrict__ out) {
    const int q = blockIdx.x;
    const int tid = threadIdx.x;
    const int lane = tid & 31;
    const int w = tid >> 5;
    __shared__ float s_v[NCAND];
    __shared__ int   s_i[NCAND];
    __shared__ float s_min, s_best, s_part[4];
    __shared__ int   s_bidx;
    if (tid < NCAND) { s_v[tid] = g_pv[tid * Bq + q]; s_i[tid] = g_pi[tid * Bq + q]; }
    if (tid == 0) { s_best = FLT_MAX; s_bidx = 0x7fffffff; }
    __syncthreads();
    if (tid == 0) {
        float m = FLT_MAX;
        for (int c = 0; c < NCAND; c++) m = fminf(m, s_v[c]);
        s_min = m;
    }
    __syncthreads();
    float4 q4 = reinterpret_cast<const float4*>(Q + (size_t)q * Dd)[tid];
    for (int c = 0; c < NCAND; c++) {
        float vc = s_v[c]; int ic = s_i[c];
        if (ic >= 0 && vc <= s_min + MARGIN) {        // uniform across block
            float4 b4 = reinterpret_cast<const float4*>(Bf + (size_t)ic * Dd)[tid];
            float p = q4.x * b4.x + q4.y * b4.y + q4.z * b4.z + q4.w * b4.w;
#pragma unroll
            for (int o = 16; o > 0; o >>= 1) p += __shfl_down_sync(0xffffffffu, p, o);
            if (lane == 0) s_part[w] = p;
            __syncthreads();
            if (tid == 0) {
                float dot = s_part[0] + s_part[1] + s_part[2] + s_part[3];
                float d = g_b2[ic] - 2.f * dot;
                if (d < s_best || (d == s_best && ic < s_bidx)) { s_best = d; s_bidx = ic; }
            }
            __syncthreads();
        }
    }
    __syncthreads();
    int bi = s_bidx;
    reinterpret_cast<float4*>(out + (size_t)q * Dd)[tid] =
        reinterpret_cast<const float4*>(Bf + (size_t)bi * Dd)[tid];
}

// ---------------------------------------------------------------------------
extern "C" void kernel_launch(void* const* d_in, const int* in_sizes, int n_in,
                              void* d_out, int out_size) {
    const float* Q  = (const float*)d_in[0];   // [2048, 512]
    const float* Bf = (const float*)d_in[1];   // [100000, 512]
    float* out = (float*)d_out;                // [2048, 512]

    cudaFuncSetAttribute(knn_mma_kernel,
                         cudaFuncAttributeMaxDynamicSharedMemorySize, SMEM_TOTAL);

    knn_convq_kernel<<<(Bq * Dd / 4) / 256, 256>>>(Q);
    knn_convb_kernel<<<(Nn + 7) / 8, 256>>>(Bf);
    dim3 grid(Bq / BM, NSPLIT);
    knn_mma_kernel<<<grid, NT, SMEM_TOTAL>>>();
    knn_rescore_kernel<<<Bq, 128>>>(Q, Bf, out);
}